// round 2
// baseline (speedup 1.0000x reference)
#include <cuda_runtime.h>
#include <cuda_bf16.h>
#include <cstdint>

#define BB 8
#define CC 256
#define HWN 16384
#define KK 64
#define EPS 1e-5f
#define PTILE 128
#define XS_STR 136   // xs[c][p] row stride
#define AT_STR 133   // atT[k][p] row stride

// ---------------- device scratch (no allocation) ----------------
__device__ float g_attn[(size_t)BB * KK * HWN];   // [b][k][n]  32MB
__device__ float g_cluster[BB * KK * CC];
__device__ float g_A[BB * KK];
__device__ float g_S2[BB * KK * KK];
__device__ float g_centT[CC * KK];                // centers transposed [c][k]
__device__ float g_ref[BB * KK * CC];             // silu(dwconv) [b][k][c]
__device__ float g_Mhat[BB * KK * CC];            // alpha * Mc  [b][k][o]
__device__ float g_Bc[BB * CC];

// ---------------- init: zero accumulators + transpose centers ----------------
__global__ void k_init(const float* __restrict__ centers) {
    int i = blockIdx.x * blockDim.x + threadIdx.x;
    int st = gridDim.x * blockDim.x;
    for (int t = i; t < BB * KK * CC; t += st) g_cluster[t] = 0.f;
    for (int t = i; t < BB * KK * KK; t += st) g_S2[t] = 0.f;
    for (int t = i; t < BB * KK; t += st) g_A[t] = 0.f;
    for (int t = i; t < KK * CC; t += st) {
        int k = t >> 8, c = t & 255;
        g_centT[c * KK + k] = centers[t];
    }
}

// ---------------- pass 1: sim -> softmax -> attn, A, S2, cluster ----------------
__global__ __launch_bounds__(512, 1) void k1(const float* __restrict__ x) {
    extern __shared__ float s1[];
    float* xs  = s1;                    // [256][136] : xs[c][p]
    float* atT = s1 + CC * XS_STR;      // [64][133]  : atT[k][p]

    const int b = blockIdx.y;
    const int pix0 = blockIdx.x * PTILE;
    const int tid = threadIdx.x;
    const float* xb = x + (size_t)b * CC * HWN;

    // load x tile: 8192 float4 (16 per thread), xs[c][p]
#pragma unroll
    for (int it = 0; it < 16; it++) {
        int idx = it * 512 + tid;
        int c = idx >> 5, p4 = idx & 31;
        float4 v = __ldcs((const float4*)(xb + (size_t)c * HWN + pix0) + p4);
        ((float4*)(xs + c * XS_STR))[p4] = v;
    }
    __syncthreads();

    // sim: thread = (pixel p, 16-k slab), centers via L1-resident global
    {
        int p = tid & 127;
        int k0 = (tid >> 7) * 16;
        float acc[16];
#pragma unroll
        for (int i = 0; i < 16; i++) acc[i] = 0.f;
        for (int c = 0; c < CC; c++) {
            float xv = xs[c * XS_STR + p];
            const float4* cr = (const float4*)(g_centT + c * KK + k0);
            float4 c0 = __ldg(cr + 0), c1 = __ldg(cr + 1);
            float4 c2 = __ldg(cr + 2), c3 = __ldg(cr + 3);
            acc[0]  = fmaf(xv, c0.x, acc[0]);  acc[1]  = fmaf(xv, c0.y, acc[1]);
            acc[2]  = fmaf(xv, c0.z, acc[2]);  acc[3]  = fmaf(xv, c0.w, acc[3]);
            acc[4]  = fmaf(xv, c1.x, acc[4]);  acc[5]  = fmaf(xv, c1.y, acc[5]);
            acc[6]  = fmaf(xv, c1.z, acc[6]);  acc[7]  = fmaf(xv, c1.w, acc[7]);
            acc[8]  = fmaf(xv, c2.x, acc[8]);  acc[9]  = fmaf(xv, c2.y, acc[9]);
            acc[10] = fmaf(xv, c2.z, acc[10]); acc[11] = fmaf(xv, c2.w, acc[11]);
            acc[12] = fmaf(xv, c3.x, acc[12]); acc[13] = fmaf(xv, c3.y, acc[13]);
            acc[14] = fmaf(xv, c3.z, acc[14]); acc[15] = fmaf(xv, c3.w, acc[15]);
        }
#pragma unroll
        for (int i = 0; i < 16; i++)
            atT[(k0 + i) * AT_STR + p] = acc[i] * 0.0625f;   // * C^-0.5
    }
    __syncthreads();

    // softmax over k per pixel; write attn [b][k][n] coalesced
    if (tid < 128) {
        int p = tid;
        float v[KK];
        float m = -1e30f;
#pragma unroll
        for (int k = 0; k < KK; k++) { v[k] = atT[k * AT_STR + p]; m = fmaxf(m, v[k]); }
        float ssum = 0.f;
#pragma unroll
        for (int k = 0; k < KK; k++) { v[k] = __expf(v[k] - m); ssum += v[k]; }
        float inv = 1.f / ssum;
        float* ab = g_attn + (size_t)b * KK * HWN + pix0 + p;
#pragma unroll
        for (int k = 0; k < KK; k++) {
            v[k] *= inv;
            atT[k * AT_STR + p] = v[k];
            ab[(size_t)k * HWN] = v[k];
        }
    }
    __syncthreads();

    // A: per-k sums
    if (tid < KK) {
        float ssum = 0.f;
        for (int p = 0; p < PTILE; p++) ssum += atT[tid * AT_STR + p];
        atomicAdd(&g_A[b * KK + tid], ssum);
    }

    // S2 = attn^T attn (2i x 4j per thread)
    {
        int i0 = (tid & 31) * 2;
        int j0 = (tid >> 5) * 4;
        float acc[2][4] = {};
        for (int p = 0; p < PTILE; p++) {
            float ai0 = atT[i0 * AT_STR + p];
            float ai1 = atT[(i0 + 1) * AT_STR + p];
            float aj0 = atT[(j0 + 0) * AT_STR + p];
            float aj1 = atT[(j0 + 1) * AT_STR + p];
            float aj2 = atT[(j0 + 2) * AT_STR + p];
            float aj3 = atT[(j0 + 3) * AT_STR + p];
            acc[0][0] = fmaf(ai0, aj0, acc[0][0]); acc[0][1] = fmaf(ai0, aj1, acc[0][1]);
            acc[0][2] = fmaf(ai0, aj2, acc[0][2]); acc[0][3] = fmaf(ai0, aj3, acc[0][3]);
            acc[1][0] = fmaf(ai1, aj0, acc[1][0]); acc[1][1] = fmaf(ai1, aj1, acc[1][1]);
            acc[1][2] = fmaf(ai1, aj2, acc[1][2]); acc[1][3] = fmaf(ai1, aj3, acc[1][3]);
        }
#pragma unroll
        for (int i = 0; i < 2; i++)
#pragma unroll
            for (int j = 0; j < 4; j++)
                atomicAdd(&g_S2[(b * KK + i0 + i) * KK + j0 + j], acc[i][j]);
    }

    // cluster[k][c] += sum_p attn[k][p] * x[c][p]  (2k x 16c per thread)
    {
        int k0 = (tid & 31) * 2;
        int c0 = (tid >> 5) * 16;
        float acc[2][16] = {};
        for (int p = 0; p < PTILE; p++) {
            float a0 = atT[k0 * AT_STR + p];
            float a1 = atT[(k0 + 1) * AT_STR + p];
#pragma unroll
            for (int j = 0; j < 16; j++) {
                float xv = xs[(c0 + j) * XS_STR + p];
                acc[0][j] = fmaf(a0, xv, acc[0][j]);
                acc[1][j] = fmaf(a1, xv, acc[1][j]);
            }
        }
#pragma unroll
        for (int i = 0; i < 2; i++)
#pragma unroll
            for (int j = 0; j < 16; j++)
                atomicAdd(&g_cluster[(b * KK + k0 + i) * CC + c0 + j], acc[i][j]);
    }
}

// ---------------- pass 2a: depthwise 7x7 on 8x8 grid + bias + silu ----------------
__global__ __launch_bounds__(256) void k2a(const float* __restrict__ dw_w,
                                           const float* __restrict__ dw_b) {
    extern __shared__ float s2[];
    float* cl  = s2;             // [64][256]
    float* dws = s2 + KK * CC;   // [256][49]
    int b = blockIdx.x, tid = threadIdx.x;
    for (int i = tid; i < KK * CC; i += 256) cl[i] = g_cluster[b * KK * CC + i];
    for (int i = tid; i < CC * 49; i += 256) dws[i] = dw_w[i];
    __syncthreads();
    int c = tid;
    float bias = dw_b[c];
    for (int pos = 0; pos < 64; pos++) {
        int i = pos >> 3, j = pos & 7;
        float sacc = bias;
        for (int di = 0; di < 7; di++) {
            int ii = i + di - 3;
            if (ii < 0 || ii >= 8) continue;
            for (int dj = 0; dj < 7; dj++) {
                int jj = j + dj - 3;
                if (jj < 0 || jj >= 8) continue;
                sacc = fmaf(cl[(ii * 8 + jj) * CC + c], dws[c * 49 + di * 7 + dj], sacc);
            }
        }
        float r = sacc / (1.f + expf(-sacc));   // silu
        g_ref[(b * KK + pos) * CC + c] = r;
    }
}

// ---------------- pass 2b: M = refined @ pw^T, analytic GN stats, Mhat/Bc ----------------
__global__ __launch_bounds__(256) void k2b(const float* __restrict__ pw_w,
                                           const float* __restrict__ pw_b,
                                           const float* __restrict__ gn_g,
                                           const float* __restrict__ gn_b) {
    extern __shared__ float s3[];
    float* rf     = s3;                // 16384
    float* S2s    = rf + 16384;        // 4096
    float* pwS    = S2s + 4096;        // 32*257 = 8224
    float* Ms     = pwS + 8224;        // 64*33 = 2112
    float* As     = Ms + 2112;         // 64
    float* abar   = As + 64;           // 32
    float* ybar   = abar + 32;         // 32
    float* qs     = ybar + 32;         // 32
    float* alphaS = qs + 32;           // 32
    float* mug    = alphaS + 32;       // 4
    float* rstdg  = mug + 4;           // 4

    const int b = blockIdx.y;
    const int o0 = blockIdx.x * 32;
    const int tid = threadIdx.x;

    for (int i = tid; i < KK * CC; i += 256) rf[i] = g_ref[b * KK * CC + i];
    for (int i = tid; i < KK * KK; i += 256) S2s[i] = g_S2[b * KK * KK + i];
    if (tid < KK) As[tid] = g_A[b * KK + tid];
    for (int i = tid; i < 32 * CC; i += 256) {
        int o = i >> 8, c = i & 255;
        pwS[o * 257 + c] = pw_w[(o0 + o) * CC + c];
    }
    __syncthreads();

    // M[k][o] = sum_c rf[k][c] * pw[o][c]
    {
        int oG = tid & 31, k0 = (tid >> 5) * 8;
        float acc[8] = {};
        for (int c = 0; c < CC; c++) {
            float pv = pwS[oG * 257 + c];
#pragma unroll
            for (int i = 0; i < 8; i++)
                acc[i] = fmaf(rf[(k0 + i) * CC + c], pv, acc[i]);
        }
#pragma unroll
        for (int i = 0; i < 8; i++) Ms[(k0 + i) * 33 + oG] = acc[i];
    }
    __syncthreads();

    // per-channel mean of y:  ybar_o = pw_b + sum_k (A_k/N) M[k][o]
    if (tid < 32) {
        float ssum = 0.f;
        for (int k = 0; k < KK; k++) ssum = fmaf(As[k], Ms[k * 33 + tid], ssum);
        float ab = ssum * (1.f / (float)HWN);
        abar[tid] = ab;
        ybar[tid] = pw_b[o0 + tid] + ab;
    }
    __syncthreads();

    // center: Mc = M - abar_o  (valid since sum_k attn = 1)
    for (int i = tid; i < KK * 32; i += 256) {
        int k = i >> 5, o = i & 31;
        Ms[k * 33 + o] -= abar[o];
    }
    __syncthreads();

    // q_o = Mc_o^T S2 Mc_o = sum_n (y_no - ybar_o)^2
    if (tid < 32) {
        float q = 0.f;
        for (int k = 0; k < KK; k++) {
            float t = 0.f;
            for (int k2 = 0; k2 < KK; k2++)
                t = fmaf(S2s[k * KK + k2], Ms[k2 * 33 + tid], t);
            q = fmaf(Ms[k * 33 + tid], t, q);
        }
        qs[tid] = q;
    }
    __syncthreads();

    // group stats (4 groups of 8 channels in this 32-o tile)
    if (tid < 4) {
        float mu = 0.f;
#pragma unroll
        for (int j = 0; j < 8; j++) mu += ybar[tid * 8 + j];
        mu *= 0.125f;
        float v = 0.f, vq = 0.f;
#pragma unroll
        for (int j = 0; j < 8; j++) {
            float d = ybar[tid * 8 + j] - mu;
            v = fmaf(d, d, v);
            vq += qs[tid * 8 + j];
        }
        v = v * 0.125f + vq * (1.f / (8.f * (float)HWN));
        mug[tid] = mu;
        rstdg[tid] = rsqrtf(v + EPS);
    }
    __syncthreads();

    if (tid < 32) {
        int o = o0 + tid, g = tid >> 3;
        float a = gn_g[o] * rstdg[g];
        alphaS[tid] = a;
        g_Bc[b * CC + o] = gn_b[o] + a * (ybar[tid] - mug[g]);
    }
    __syncthreads();

    for (int i = tid; i < KK * 32; i += 256) {
        int k = i >> 5, oG = i & 31;
        g_Mhat[(b * KK + k) * CC + o0 + oG] = alphaS[oG] * Ms[k * 33 + oG];
    }
}

// ---------------- pass 3: out = x + attn @ Mhat + Bc ----------------
__global__ __launch_bounds__(512, 1) void k3(const float* __restrict__ x,
                                             float* __restrict__ out) {
    extern __shared__ float s4[];
    float* atS = s4;               // [64][132]
    float* MhS = s4 + KK * 132;    // [64][256]
    float* BcS = MhS + KK * CC;    // [256]

    const int b = blockIdx.y;
    const int pix0 = blockIdx.x * PTILE;
    const int tid = threadIdx.x;

#pragma unroll
    for (int it = 0; it < 4; it++) {
        int idx = it * 512 + tid;          // 0..2047
        int k = idx >> 5, p4 = idx & 31;
        float4 v = *((const float4*)(g_attn + (size_t)(b * KK + k) * HWN + pix0) + p4);
        ((float4*)(atS + k * 132))[p4] = v;
    }
#pragma unroll
    for (int it = 0; it < 8; it++) {
        int idx = it * 512 + tid;          // 0..4095 float4
        ((float4*)MhS)[idx] = ((const float4*)(g_Mhat + (size_t)b * KK * CC))[idx];
    }
    if (tid < CC) BcS[tid] = g_Bc[b * CC + tid];
    __syncthreads();

    int p = tid & 127;
    int c0 = (tid >> 7) * 64;
    float acc[64];
#pragma unroll
    for (int j = 0; j < 64; j++) acc[j] = BcS[c0 + j];

    for (int k = 0; k < KK; k++) {
        float a = atS[k * 132 + p];
        const float4* mh = (const float4*)(MhS + k * CC + c0);
#pragma unroll
        for (int j4 = 0; j4 < 16; j4++) {
            float4 m = mh[j4];
            acc[4 * j4 + 0] = fmaf(a, m.x, acc[4 * j4 + 0]);
            acc[4 * j4 + 1] = fmaf(a, m.y, acc[4 * j4 + 1]);
            acc[4 * j4 + 2] = fmaf(a, m.z, acc[4 * j4 + 2]);
            acc[4 * j4 + 3] = fmaf(a, m.w, acc[4 * j4 + 3]);
        }
    }

    const float* xb = x + ((size_t)b * CC + c0) * HWN + pix0 + p;
    float* ob = out + ((size_t)b * CC + c0) * HWN + pix0 + p;
#pragma unroll
    for (int j = 0; j < 64; j++)
        ob[(size_t)j * HWN] = __ldcs(xb + (size_t)j * HWN) + acc[j];
}

// ---------------- launch ----------------
extern "C" void kernel_launch(void* const* d_in, const int* in_sizes, int n_in,
                              void* d_out, int out_size) {
    const float* x       = (const float*)d_in[0];
    const float* centers = (const float*)d_in[1];
    const float* dw_w    = (const float*)d_in[2];
    const float* dw_b    = (const float*)d_in[3];
    const float* pw_w    = (const float*)d_in[4];
    const float* pw_b    = (const float*)d_in[5];
    const float* gn_g    = (const float*)d_in[6];
    const float* gn_b    = (const float*)d_in[7];
    float* out = (float*)d_out;

    const int SM1  = (CC * XS_STR + KK * AT_STR) * 4;                  // 173312
    const int SM2A = (KK * CC + CC * 49) * 4;                          // 115712
    const int SM2B = (16384 + 4096 + 8224 + 2112 + 64 + 32 * 4 + 8) * 4; // 124064
    const int SM3  = (KK * 132 + KK * CC + CC) * 4;                    // 100352

    cudaFuncSetAttribute(k1,  cudaFuncAttributeMaxDynamicSharedMemorySize, SM1);
    cudaFuncSetAttribute(k2a, cudaFuncAttributeMaxDynamicSharedMemorySize, SM2A);
    cudaFuncSetAttribute(k2b, cudaFuncAttributeMaxDynamicSharedMemorySize, SM2B);
    cudaFuncSetAttribute(k3,  cudaFuncAttributeMaxDynamicSharedMemorySize, SM3);

    k_init<<<256, 256>>>(centers);
    k1<<<dim3(HWN / PTILE, BB), 512, SM1>>>(x);
    k2a<<<BB, 256, SM2A>>>(dw_w, dw_b);
    k2b<<<dim3(8, BB), 256, SM2B>>>(pw_w, pw_b, gn_g, gn_b);
    k3<<<dim3(HWN / PTILE, BB), 512, SM3>>>(x, out);
}

// round 3
// speedup vs baseline: 1.1974x; 1.1974x over previous
#include <cuda_runtime.h>
#include <cuda_bf16.h>
#include <cstdint>

#define BB 8
#define CC 256
#define HWN 16384
#define KK 64
#define EPS 1e-5f
#define PTILE 128
#define XS_STR 132   // xs[c][p] row stride (mult of 4)
#define AT_STR 132   // atT[k][p] row stride (mult of 4)

typedef unsigned long long ull;

// ---------------- f32x2 helpers ----------------
__device__ __forceinline__ ull pk2(float lo, float hi) {
    ull d; asm("mov.b64 %0, {%1, %2};" : "=l"(d) : "f"(lo), "f"(hi)); return d;
}
__device__ __forceinline__ float2 unpk(ull v) {
    float2 r; asm("mov.b64 {%0, %1}, %2;" : "=f"(r.x), "=f"(r.y) : "l"(v)); return r;
}
__device__ __forceinline__ void ffma2(ull& d, ull a, ull b) {
    asm("fma.rn.f32x2 %0, %1, %2, %0;" : "+l"(d) : "l"(a), "l"(b));
}

// ---------------- device scratch (no allocation) ----------------
__device__ float g_attn[(size_t)BB * KK * HWN];   // [b][k][n]  32MB
__device__ float g_cluster[BB * KK * CC];
__device__ float g_A[BB * KK];
__device__ float g_S2[BB * KK * KK];
__device__ float g_centT[CC * KK];                // centers transposed [c][k]
__device__ float g_ref[BB * KK * CC];             // silu(dwconv) [b][k][c]
__device__ float g_Mhat[BB * KK * CC];            // alpha * Mc  [b][k][o]
__device__ float g_Bc[BB * CC];

// ---------------- init: zero accumulators + transpose centers ----------------
__global__ void k_init(const float* __restrict__ centers) {
    int i = blockIdx.x * blockDim.x + threadIdx.x;
    int st = gridDim.x * blockDim.x;
    for (int t = i; t < BB * KK * CC; t += st) g_cluster[t] = 0.f;
    for (int t = i; t < BB * KK * KK; t += st) g_S2[t] = 0.f;
    for (int t = i; t < BB * KK; t += st) g_A[t] = 0.f;
    for (int t = i; t < KK * CC; t += st) {
        int k = t >> 8, c = t & 255;
        g_centT[c * KK + k] = centers[t];
    }
}

// ---------------- pass 1: sim -> softmax -> attn, A, S2, cluster ----------------
__global__ __launch_bounds__(512, 1) void k1(const float* __restrict__ x) {
    extern __shared__ float s1[];
    float* xs  = s1;                    // [256][132] : xs[c][p]
    float* atT = s1 + CC * XS_STR;      // [64][132]  : atT[k][p]

    const int b = blockIdx.y;
    const int pix0 = blockIdx.x * PTILE;
    const int tid = threadIdx.x;
    const float* xb = x + (size_t)b * CC * HWN;

    // load x tile: 8192 float4 (16 per thread), xs[c][p]
#pragma unroll
    for (int it = 0; it < 16; it++) {
        int idx = it * 512 + tid;
        int c = idx >> 5, p4 = idx & 31;
        float4 v = __ldcs((const float4*)(xb + (size_t)c * HWN + pix0) + p4);
        *((float4*)(xs + c * XS_STR) + p4) = v;
    }
    __syncthreads();

    // --- sim: thread = (pixel quad pq, 4-k slab ks). Center load is warp-uniform. ---
    {
        const int pq = tid & 31, ks = tid >> 5;
        const int p0 = pq * 4, k0 = ks * 4;
        ull a00 = 0, a01 = 0, a10 = 0, a11 = 0, a20 = 0, a21 = 0, a30 = 0, a31 = 0;
        const float* xcol = xs + p0;
#pragma unroll 4
        for (int c = 0; c < CC; c++) {
            float4 xq = *(const float4*)(xcol + c * XS_STR);
            ulonglong2 cv = __ldg((const ulonglong2*)(g_centT + c * KK + k0));
            ull x0 = pk2(xq.x, xq.x), x1 = pk2(xq.y, xq.y);
            ull x2 = pk2(xq.z, xq.z), x3 = pk2(xq.w, xq.w);
            ffma2(a00, x0, cv.x); ffma2(a01, x0, cv.y);
            ffma2(a10, x1, cv.x); ffma2(a11, x1, cv.y);
            ffma2(a20, x2, cv.x); ffma2(a21, x2, cv.y);
            ffma2(a30, x3, cv.x); ffma2(a31, x3, cv.y);
        }
        const float s = 0.0625f;   // C^-0.5
        float2 t;
        t = unpk(a00); atT[(k0+0)*AT_STR + p0+0] = t.x*s; atT[(k0+1)*AT_STR + p0+0] = t.y*s;
        t = unpk(a01); atT[(k0+2)*AT_STR + p0+0] = t.x*s; atT[(k0+3)*AT_STR + p0+0] = t.y*s;
        t = unpk(a10); atT[(k0+0)*AT_STR + p0+1] = t.x*s; atT[(k0+1)*AT_STR + p0+1] = t.y*s;
        t = unpk(a11); atT[(k0+2)*AT_STR + p0+1] = t.x*s; atT[(k0+3)*AT_STR + p0+1] = t.y*s;
        t = unpk(a20); atT[(k0+0)*AT_STR + p0+2] = t.x*s; atT[(k0+1)*AT_STR + p0+2] = t.y*s;
        t = unpk(a21); atT[(k0+2)*AT_STR + p0+2] = t.x*s; atT[(k0+3)*AT_STR + p0+2] = t.y*s;
        t = unpk(a30); atT[(k0+0)*AT_STR + p0+3] = t.x*s; atT[(k0+1)*AT_STR + p0+3] = t.y*s;
        t = unpk(a31); atT[(k0+2)*AT_STR + p0+3] = t.x*s; atT[(k0+3)*AT_STR + p0+3] = t.y*s;
    }
    __syncthreads();

    // --- softmax over k per pixel ---
    if (tid < 128) {
        int p = tid;
        float v[KK];
        float m = -1e30f;
#pragma unroll
        for (int k = 0; k < KK; k++) { v[k] = atT[k * AT_STR + p]; m = fmaxf(m, v[k]); }
        float ssum = 0.f;
#pragma unroll
        for (int k = 0; k < KK; k++) { v[k] = __expf(v[k] - m); ssum += v[k]; }
        float inv = 1.f / ssum;
#pragma unroll
        for (int k = 0; k < KK; k++) atT[k * AT_STR + p] = v[k] * inv;
    }
    __syncthreads();

    // --- attn writeout (vectorized, coalesced) ---
#pragma unroll
    for (int it = 0; it < 4; it++) {
        int idx = it * 512 + tid;          // 0..2047
        int k = idx >> 5, p4 = idx & 31;
        float4 v = *((const float4*)(atT + k * AT_STR) + p4);
        *((float4*)(g_attn + (size_t)(b * KK + k) * HWN + pix0) + p4) = v;
    }

    // --- A: per-k sums ---
    if (tid < KK) {
        float ssum = 0.f;
        for (int p = 0; p < PTILE; p++) ssum += atT[tid * AT_STR + p];
        atomicAdd(&g_A[b * KK + tid], ssum);
    }

    // --- S2 = attn^T attn (f32x2 over pixel pairs) ---
    {
        const int i0 = (tid & 31) * 2;
        const int j0 = (tid >> 5) * 4;     // warp-uniform -> aj loads broadcast
        ull acc[2][4] = {};
        for (int p = 0; p < PTILE; p += 4) {
            ulonglong2 ai0 = *(const ulonglong2*)(atT + i0 * AT_STR + p);
            ulonglong2 ai1 = *(const ulonglong2*)(atT + (i0 + 1) * AT_STR + p);
#pragma unroll
            for (int j = 0; j < 4; j++) {
                ulonglong2 aj = *(const ulonglong2*)(atT + (j0 + j) * AT_STR + p);
                ffma2(acc[0][j], ai0.x, aj.x); ffma2(acc[0][j], ai0.y, aj.y);
                ffma2(acc[1][j], ai1.x, aj.x); ffma2(acc[1][j], ai1.y, aj.y);
            }
        }
#pragma unroll
        for (int i = 0; i < 2; i++)
#pragma unroll
            for (int j = 0; j < 4; j++) {
                float2 v = unpk(acc[i][j]);
                atomicAdd(&g_S2[(b * KK + i0 + i) * KK + j0 + j], v.x + v.y);
            }
    }

    // --- cluster[k][c] += sum_p attn[k][p]*x[c][p] (f32x2 over pixel pairs) ---
    {
        const int k0 = (tid & 31) * 2;
        const int c0 = (tid >> 5) * 16;    // warp-uniform -> x loads broadcast
        ull acc[2][16] = {};
        for (int p = 0; p < PTILE; p += 4) {
            ulonglong2 ak0 = *(const ulonglong2*)(atT + k0 * AT_STR + p);
            ulonglong2 ak1 = *(const ulonglong2*)(atT + (k0 + 1) * AT_STR + p);
#pragma unroll
            for (int j = 0; j < 16; j++) {
                ulonglong2 xv = *(const ulonglong2*)(xs + (c0 + j) * XS_STR + p);
                ffma2(acc[0][j], ak0.x, xv.x); ffma2(acc[0][j], ak0.y, xv.y);
                ffma2(acc[1][j], ak1.x, xv.x); ffma2(acc[1][j], ak1.y, xv.y);
            }
        }
#pragma unroll
        for (int i = 0; i < 2; i++)
#pragma unroll
            for (int j = 0; j < 16; j++) {
                float2 v = unpk(acc[i][j]);
                atomicAdd(&g_cluster[(b * KK + k0 + i) * CC + c0 + j], v.x + v.y);
            }
    }
}

// ---------------- pass 2a: depthwise 7x7 on 8x8 grid + bias + silu ----------------
__global__ __launch_bounds__(256) void k2a(const float* __restrict__ dw_w,
                                           const float* __restrict__ dw_b) {
    extern __shared__ float s2[];
    float* cl  = s2;             // [64][256]
    float* dws = s2 + KK * CC;   // [256][49]
    int b = blockIdx.x, tid = threadIdx.x;
    int pos0 = blockIdx.y * 16;
    for (int i = tid; i < KK * CC; i += 256) cl[i] = g_cluster[b * KK * CC + i];
    for (int i = tid; i < CC * 49; i += 256) dws[i] = dw_w[i];
    __syncthreads();
    int c = tid;
    float bias = dw_b[c];
    for (int pos = pos0; pos < pos0 + 16; pos++) {
        int i = pos >> 3, j = pos & 7;
        float sacc = bias;
        for (int di = 0; di < 7; di++) {
            int ii = i + di - 3;
            if (ii < 0 || ii >= 8) continue;
            for (int dj = 0; dj < 7; dj++) {
                int jj = j + dj - 3;
                if (jj < 0 || jj >= 8) continue;
                sacc = fmaf(cl[(ii * 8 + jj) * CC + c], dws[c * 49 + di * 7 + dj], sacc);
            }
        }
        float r = sacc / (1.f + expf(-sacc));   // silu
        g_ref[(b * KK + pos) * CC + c] = r;
    }
}

// ---------------- pass 2b: M = refined @ pw^T, analytic GN stats, Mhat/Bc ----------------
__global__ __launch_bounds__(256) void k2b(const float* __restrict__ pw_w,
                                           const float* __restrict__ pw_b,
                                           const float* __restrict__ gn_g,
                                           const float* __restrict__ gn_b) {
    extern __shared__ float s3[];
    float* rf     = s3;                // 16384
    float* S2s    = rf + 16384;        // 4096
    float* pwS    = S2s + 4096;        // 32*257 = 8224 (later reused as T[k][o] 64*33)
    float* Ms     = pwS + 8224;        // 64*33 = 2112
    float* As     = Ms + 2112;         // 64
    float* abar   = As + 64;           // 32
    float* ybar   = abar + 32;         // 32
    float* qs     = ybar + 32;         // 32
    float* alphaS = qs + 32;           // 32
    float* mug    = alphaS + 32;       // 4
    float* rstdg  = mug + 4;           // 4

    const int b = blockIdx.y;
    const int o0 = blockIdx.x * 32;
    const int tid = threadIdx.x;

    for (int i = tid; i < KK * CC; i += 256) rf[i] = g_ref[b * KK * CC + i];
    for (int i = tid; i < KK * KK; i += 256) S2s[i] = g_S2[b * KK * KK + i];
    if (tid < KK) As[tid] = g_A[b * KK + tid];
    for (int i = tid; i < 32 * CC; i += 256) {
        int o = i >> 8, c = i & 255;
        pwS[o * 257 + c] = pw_w[(o0 + o) * CC + c];
    }
    __syncthreads();

    // M[k][o] = sum_c rf[k][c] * pw[o][c]
    {
        int oG = tid & 31, k0 = (tid >> 5) * 8;
        float acc[8] = {};
        for (int c = 0; c < CC; c++) {
            float pv = pwS[oG * 257 + c];
#pragma unroll
            for (int i = 0; i < 8; i++)
                acc[i] = fmaf(rf[(k0 + i) * CC + c], pv, acc[i]);
        }
#pragma unroll
        for (int i = 0; i < 8; i++) Ms[(k0 + i) * 33 + oG] = acc[i];
    }
    __syncthreads();

    // ybar_o = pw_b + sum_k (A_k/N) M[k][o]
    if (tid < 32) {
        float ssum = 0.f;
        for (int k = 0; k < KK; k++) ssum = fmaf(As[k], Ms[k * 33 + tid], ssum);
        float ab = ssum * (1.f / (float)HWN);
        abar[tid] = ab;
        ybar[tid] = pw_b[o0 + tid] + ab;
    }
    __syncthreads();

    // center: Mc = M - abar_o  (valid since sum_k attn = 1)
    for (int i = tid; i < KK * 32; i += 256) {
        int k = i >> 5, o = i & 31;
        Ms[k * 33 + o] -= abar[o];
    }
    __syncthreads();

    // T[k][o] = sum_k2 S2[k][k2] * Mc[k2][o]   (parallel over 256 threads; reuse pwS)
    for (int i = tid; i < KK * 32; i += 256) {
        int k = i >> 5, o = i & 31;
        float t = 0.f;
        for (int k2 = 0; k2 < KK; k2++)
            t = fmaf(S2s[k * KK + k2], Ms[k2 * 33 + o], t);
        pwS[k * 33 + o] = t;
    }
    __syncthreads();

    // q_o = sum_k Mc[k][o] * T[k][o]
    if (tid < 32) {
        float q = 0.f;
        for (int k = 0; k < KK; k++)
            q = fmaf(Ms[k * 33 + tid], pwS[k * 33 + tid], q);
        qs[tid] = q;
    }
    __syncthreads();

    // group stats (4 groups of 8 channels in this 32-o tile)
    if (tid < 4) {
        float mu = 0.f;
#pragma unroll
        for (int j = 0; j < 8; j++) mu += ybar[tid * 8 + j];
        mu *= 0.125f;
        float v = 0.f, vq = 0.f;
#pragma unroll
        for (int j = 0; j < 8; j++) {
            float d = ybar[tid * 8 + j] - mu;
            v = fmaf(d, d, v);
            vq += qs[tid * 8 + j];
        }
        v = v * 0.125f + vq * (1.f / (8.f * (float)HWN));
        mug[tid] = mu;
        rstdg[tid] = rsqrtf(v + EPS);
    }
    __syncthreads();

    if (tid < 32) {
        int o = o0 + tid, g = tid >> 3;
        float a = gn_g[o] * rstdg[g];
        alphaS[tid] = a;
        g_Bc[b * CC + o] = gn_b[o] + a * (ybar[tid] - mug[g]);
    }
    __syncthreads();

    for (int i = tid; i < KK * 32; i += 256) {
        int k = i >> 5, oG = i & 31;
        g_Mhat[(b * KK + k) * CC + o0 + oG] = alphaS[oG] * Ms[k * 33 + oG];
    }
}

// ---------------- pass 3: out = x + attn @ Mhat + Bc ----------------
__global__ __launch_bounds__(512, 1) void k3(const float* __restrict__ x,
                                             float* __restrict__ out) {
    extern __shared__ float s4[];
    float* atS = s4;               // [64][132]
    float* MhS = s4 + KK * 132;    // [64][256]
    float* BcS = MhS + KK * CC;    // [256]

    const int b = blockIdx.y;
    const int pix0 = blockIdx.x * PTILE;
    const int tid = threadIdx.x;

#pragma unroll
    for (int it = 0; it < 4; it++) {
        int idx = it * 512 + tid;          // 0..2047
        int k = idx >> 5, p4 = idx & 31;
        float4 v = *((const float4*)(g_attn + (size_t)(b * KK + k) * HWN + pix0) + p4);
        *((float4*)(atS + k * 132) + p4) = v;
    }
#pragma unroll
    for (int it = 0; it < 8; it++) {
        int idx = it * 512 + tid;          // 0..4095 float4
        ((float4*)MhS)[idx] = ((const float4*)(g_Mhat + (size_t)b * KK * CC))[idx];
    }
    if (tid < CC) BcS[tid] = g_Bc[b * CC + tid];
    __syncthreads();

    const int p = tid & 127;
    const int c0 = (tid >> 7) * 64;
    ull acc[32];
#pragma unroll
    for (int j = 0; j < 32; j++) acc[j] = *(const ull*)(BcS + c0 + 2 * j);

    for (int k = 0; k < KK; k++) {
        float a = atS[k * 132 + p];
        ull ad = pk2(a, a);
        const ulonglong2* mh = (const ulonglong2*)(MhS + k * CC + c0);
#pragma unroll
        for (int j4 = 0; j4 < 16; j4++) {
            ulonglong2 m = mh[j4];
            ffma2(acc[2 * j4],     ad, m.x);
            ffma2(acc[2 * j4 + 1], ad, m.y);
        }
    }

    const float* xb = x + ((size_t)b * CC + c0) * HWN + pix0 + p;
    float* ob = out + ((size_t)b * CC + c0) * HWN + pix0 + p;
#pragma unroll
    for (int j = 0; j < 32; j++) {
        float2 v = unpk(acc[j]);
        size_t off0 = (size_t)(2 * j) * HWN;
        size_t off1 = (size_t)(2 * j + 1) * HWN;
        ob[off0] = __ldcs(xb + off0) + v.x;
        ob[off1] = __ldcs(xb + off1) + v.y;
    }
}

// ---------------- launch ----------------
extern "C" void kernel_launch(void* const* d_in, const int* in_sizes, int n_in,
                              void* d_out, int out_size) {
    const float* x       = (const float*)d_in[0];
    const float* centers = (const float*)d_in[1];
    const float* dw_w    = (const float*)d_in[2];
    const float* dw_b    = (const float*)d_in[3];
    const float* pw_w    = (const float*)d_in[4];
    const float* pw_b    = (const float*)d_in[5];
    const float* gn_g    = (const float*)d_in[6];
    const float* gn_b    = (const float*)d_in[7];
    float* out = (float*)d_out;

    const int SM1  = (CC * XS_STR + KK * AT_STR) * 4;                    // 168960
    const int SM2A = (KK * CC + CC * 49) * 4;                            // 115712
    const int SM2B = (16384 + 4096 + 8224 + 2112 + 64 + 32 * 4 + 8) * 4; // 124064
    const int SM3  = (KK * 132 + KK * CC + CC) * 4;                      // 100352

    cudaFuncSetAttribute(k1,  cudaFuncAttributeMaxDynamicSharedMemorySize, SM1);
    cudaFuncSetAttribute(k2a, cudaFuncAttributeMaxDynamicSharedMemorySize, SM2A);
    cudaFuncSetAttribute(k2b, cudaFuncAttributeMaxDynamicSharedMemorySize, SM2B);
    cudaFuncSetAttribute(k3,  cudaFuncAttributeMaxDynamicSharedMemorySize, SM3);

    k_init<<<256, 256>>>(centers);
    k1<<<dim3(HWN / PTILE, BB), 512, SM1>>>(x);
    k2a<<<dim3(BB, 4), 256, SM2A>>>(dw_w, dw_b);
    k2b<<<dim3(8, BB), 256, SM2B>>>(pw_w, pw_b, gn_g, gn_b);
    k3<<<dim3(HWN / PTILE, BB), 512, SM3>>>(x, out);
}

// round 4
// speedup vs baseline: 1.8847x; 1.5740x over previous
#include <cuda_runtime.h>
#include <cuda_bf16.h>
#include <cstdint>

#define BB 8
#define CC 256
#define HWN 16384
#define KK 64
#define EPS 1e-5f
#define PTILE 128
#define XS_STR 132   // xs[c][p] row stride (mult of 4)

typedef unsigned long long ull;

// ---------------- f32x2 helpers ----------------
__device__ __forceinline__ ull pk2(float lo, float hi) {
    ull d; asm("mov.b64 %0, {%1, %2};" : "=l"(d) : "f"(lo), "f"(hi)); return d;
}
__device__ __forceinline__ float2 unpk(ull v) {
    float2 r; asm("mov.b64 {%0, %1}, %2;" : "=f"(r.x), "=f"(r.y) : "l"(v)); return r;
}
__device__ __forceinline__ void ffma2(ull& d, ull a, ull b) {
    asm("fma.rn.f32x2 %0, %1, %2, %0;" : "+l"(d) : "l"(a), "l"(b));
}

// atT swizzled layout: word index for logical (k, p); row stride 128,
// 16B-chunk XOR swizzle so row-strided lane loads hit distinct banks.
__device__ __forceinline__ int atIdx(int k, int p) {
    return k * 128 + (((((p >> 2) ^ ((k >> 1) & 7))) << 2) | (p & 3));
}
__device__ __forceinline__ int atChunk(int k, int p4) {   // word index of 16B chunk
    return k * 128 + ((p4 ^ ((k >> 1) & 7)) << 2);
}

// ---------------- device scratch (no allocation) ----------------
__device__ float g_attn[(size_t)BB * KK * HWN];   // [b][k][n]  32MB
__device__ float g_cluster[BB * KK * CC];
__device__ float g_A[BB * KK];
__device__ float g_S2[BB * KK * KK];
__device__ float g_centT[CC * KK];                // centers transposed [c][k]
__device__ float g_ref[BB * KK * CC];             // silu(dwconv) [b][k][c]
__device__ float g_Mhat[BB * KK * CC];            // alpha * Mc  [b][k][o]
__device__ float g_Bc[BB * CC];

// ---------------- init ----------------
__global__ void k_init(const float* __restrict__ centers) {
    int i = blockIdx.x * blockDim.x + threadIdx.x;
    int st = gridDim.x * blockDim.x;
    for (int t = i; t < BB * KK * CC; t += st) g_cluster[t] = 0.f;
    for (int t = i; t < BB * KK * KK; t += st) g_S2[t] = 0.f;
    for (int t = i; t < BB * KK; t += st) g_A[t] = 0.f;
    for (int t = i; t < KK * CC; t += st) {
        int k = t >> 8, c = t & 255;
        g_centT[c * KK + k] = centers[t];
    }
}

// ---------------- pass 1: sim -> softmax -> attn, A, S2, cluster ----------------
__global__ __launch_bounds__(512, 1) void k1(const float* __restrict__ x) {
    extern __shared__ float s1[];
    float* xs  = s1;                    // [256][132] : xs[c][p]
    float* atT = s1 + CC * XS_STR;      // swizzled [64]x[128]

    const int b = blockIdx.y;
    const int pix0 = blockIdx.x * PTILE;
    const int tid = threadIdx.x;
    const float* xb = x + (size_t)b * CC * HWN;

    // load x tile: 8192 float4 (16 per thread), xs[c][p]
#pragma unroll
    for (int it = 0; it < 16; it++) {
        int idx = it * 512 + tid;
        int c = idx >> 5, p4 = idx & 31;
        float4 v = __ldcs((const float4*)(xb + (size_t)c * HWN + pix0) + p4);
        *((float4*)(xs + c * XS_STR) + p4) = v;
    }
    __syncthreads();

    // --- sim: 256 threads, tile = 4 pixels x 8 k ---
    if (tid < 256) {
        const int pq = tid & 31, ks = tid >> 5;
        const int p0 = pq * 4, k0 = ks * 8;
        ull acc[4][4];
#pragma unroll
        for (int i = 0; i < 4; i++)
#pragma unroll
            for (int j = 0; j < 4; j++) acc[i][j] = 0;
        const float* xcol = xs + p0;
#pragma unroll 4
        for (int c = 0; c < CC; c++) {
            float4 xq = *(const float4*)(xcol + c * XS_STR);
            ulonglong2 cv01 = __ldg((const ulonglong2*)(g_centT + c * KK + k0));
            ulonglong2 cv23 = __ldg((const ulonglong2*)(g_centT + c * KK + k0 + 4));
            ull x0 = pk2(xq.x, xq.x), x1 = pk2(xq.y, xq.y);
            ull x2 = pk2(xq.z, xq.z), x3 = pk2(xq.w, xq.w);
            ffma2(acc[0][0], x0, cv01.x); ffma2(acc[0][1], x0, cv01.y);
            ffma2(acc[0][2], x0, cv23.x); ffma2(acc[0][3], x0, cv23.y);
            ffma2(acc[1][0], x1, cv01.x); ffma2(acc[1][1], x1, cv01.y);
            ffma2(acc[1][2], x1, cv23.x); ffma2(acc[1][3], x1, cv23.y);
            ffma2(acc[2][0], x2, cv01.x); ffma2(acc[2][1], x2, cv01.y);
            ffma2(acc[2][2], x2, cv23.x); ffma2(acc[2][3], x2, cv23.y);
            ffma2(acc[3][0], x3, cv01.x); ffma2(acc[3][1], x3, cv01.y);
            ffma2(acc[3][2], x3, cv23.x); ffma2(acc[3][3], x3, cv23.y);
        }
        const float s = 0.0625f;   // C^-0.5
#pragma unroll
        for (int i = 0; i < 4; i++) {
            int p = p0 + i;
#pragma unroll
            for (int jp = 0; jp < 4; jp++) {
                float2 t = unpk(acc[i][jp]);
                atT[atIdx(k0 + 2 * jp, p)]     = t.x * s;
                atT[atIdx(k0 + 2 * jp + 1, p)] = t.y * s;
            }
        }
    }
    __syncthreads();

    // --- softmax over k per pixel ---
    if (tid < 128) {
        int p = tid;
        float v[KK];
        float m = -1e30f;
#pragma unroll
        for (int k = 0; k < KK; k++) { v[k] = atT[atIdx(k, p)]; m = fmaxf(m, v[k]); }
        float ssum = 0.f;
#pragma unroll
        for (int k = 0; k < KK; k++) { v[k] = __expf(v[k] - m); ssum += v[k]; }
        float inv = 1.f / ssum;
#pragma unroll
        for (int k = 0; k < KK; k++) atT[atIdx(k, p)] = v[k] * inv;
    }
    __syncthreads();

    // --- attn writeout (vectorized, coalesced) ---
#pragma unroll
    for (int it = 0; it < 4; it++) {
        int idx = it * 512 + tid;          // 0..2047
        int k = idx >> 5, p4 = idx & 31;
        float4 v = *(const float4*)(atT + atChunk(k, p4));
        *((float4*)(g_attn + (size_t)(b * KK + k) * HWN + pix0) + p4) = v;
    }

    // --- A: per-k sums ---
    if (tid < KK) {
        int k = tid;
        float ssum = 0.f;
        for (int p4 = 0; p4 < 32; p4++) {
            float4 v = *(const float4*)(atT + atChunk(k, p4));
            ssum += v.x + v.y + v.z + v.w;
        }
        atomicAdd(&g_A[b * KK + k], ssum);
    }

    // --- S2 = attn^T attn (f32x2 over pixel pairs, float4 atomics) ---
    {
        const int i0 = (tid & 31) * 2;
        const int j0 = (tid >> 5) * 4;     // warp-uniform -> aj broadcast
        const int si = (i0 >> 1) & 7;
        ull acc[2][4] = {};
        for (int p4 = 0; p4 < 32; p4++) {
            int ci = ((p4 ^ si) << 2);
            ulonglong2 ai0 = *(const ulonglong2*)(atT + i0 * 128 + ci);
            ulonglong2 ai1 = *(const ulonglong2*)(atT + (i0 + 1) * 128 + ci);
#pragma unroll
            for (int j = 0; j < 4; j++) {
                ulonglong2 aj = *(const ulonglong2*)(atT + atChunk(j0 + j, p4));
                ffma2(acc[0][j], ai0.x, aj.x); ffma2(acc[0][j], ai0.y, aj.y);
                ffma2(acc[1][j], ai1.x, aj.x); ffma2(acc[1][j], ai1.y, aj.y);
            }
        }
#pragma unroll
        for (int i = 0; i < 2; i++) {
            float2 v0 = unpk(acc[i][0]), v1 = unpk(acc[i][1]);
            float2 v2 = unpk(acc[i][2]), v3 = unpk(acc[i][3]);
            float4 r = make_float4(v0.x + v0.y, v1.x + v1.y, v2.x + v2.y, v3.x + v3.y);
            atomicAdd((float4*)&g_S2[(b * KK + i0 + i) * KK + j0], r);
        }
    }

    // --- cluster[k][c] += sum_p attn[k][p]*x[c][p] (float4 atomics) ---
    {
        const int k0 = (tid & 31) * 2;
        const int c0 = (tid >> 5) * 16;    // warp-uniform -> x broadcast
        const int sk = (k0 >> 1) & 7;
        ull acc[2][16] = {};
        for (int p4 = 0; p4 < 32; p4++) {
            int ck = ((p4 ^ sk) << 2);
            ulonglong2 ak0 = *(const ulonglong2*)(atT + k0 * 128 + ck);
            ulonglong2 ak1 = *(const ulonglong2*)(atT + (k0 + 1) * 128 + ck);
            const float* xp = xs + 4 * p4;
#pragma unroll
            for (int j = 0; j < 16; j++) {
                ulonglong2 xv = *(const ulonglong2*)(xp + (c0 + j) * XS_STR);
                ffma2(acc[0][j], ak0.x, xv.x); ffma2(acc[0][j], ak0.y, xv.y);
                ffma2(acc[1][j], ak1.x, xv.x); ffma2(acc[1][j], ak1.y, xv.y);
            }
        }
#pragma unroll
        for (int i = 0; i < 2; i++) {
#pragma unroll
            for (int j4 = 0; j4 < 4; j4++) {
                float2 a = unpk(acc[i][4 * j4 + 0]);
                float2 b2 = unpk(acc[i][4 * j4 + 1]);
                float2 c2 = unpk(acc[i][4 * j4 + 2]);
                float2 d2 = unpk(acc[i][4 * j4 + 3]);
                float4 r = make_float4(a.x + a.y, b2.x + b2.y, c2.x + c2.y, d2.x + d2.y);
                atomicAdd((float4*)&g_cluster[(b * KK + k0 + i) * CC + c0 + 4 * j4], r);
            }
        }
    }
}

// ---------------- pass 2a: depthwise 7x7 on 8x8 grid + bias + silu ----------------
__global__ __launch_bounds__(256) void k2a(const float* __restrict__ dw_w,
                                           const float* __restrict__ dw_b) {
    extern __shared__ float s2[];
    float* cl  = s2;             // [64][256]
    float* dws = s2 + KK * CC;   // [256][49]
    int b = blockIdx.x, tid = threadIdx.x;
    int pos0 = blockIdx.y * 4;
    for (int i = tid; i < KK * CC; i += 256) cl[i] = g_cluster[b * KK * CC + i];
    for (int i = tid; i < CC * 49; i += 256) dws[i] = dw_w[i];
    __syncthreads();
    int c = tid;
    float bias = dw_b[c];
    for (int pos = pos0; pos < pos0 + 4; pos++) {
        int i = pos >> 3, j = pos & 7;
        float sacc = bias;
        for (int di = 0; di < 7; di++) {
            int ii = i + di - 3;
            if (ii < 0 || ii >= 8) continue;
            for (int dj = 0; dj < 7; dj++) {
                int jj = j + dj - 3;
                if (jj < 0 || jj >= 8) continue;
                sacc = fmaf(cl[(ii * 8 + jj) * CC + c], dws[c * 49 + di * 7 + dj], sacc);
            }
        }
        float r = sacc / (1.f + expf(-sacc));   // silu
        g_ref[(b * KK + pos) * CC + c] = r;
    }
}

// ---------------- pass 2b: M = refined @ pw^T, analytic GN stats, Mhat/Bc ----------------
__global__ __launch_bounds__(256) void k2b(const float* __restrict__ pw_w,
                                           const float* __restrict__ pw_b,
                                           const float* __restrict__ gn_g,
                                           const float* __restrict__ gn_b) {
    extern __shared__ float s3[];
    float* rf     = s3;                // 16384
    float* S2s    = rf + 16384;        // 4096
    float* pwS    = S2s + 4096;        // 32*257 = 8224 (reused as T)
    float* Ms     = pwS + 8224;        // 64*33 = 2112
    float* As     = Ms + 2112;         // 64
    float* abar   = As + 64;           // 32
    float* ybar   = abar + 32;         // 32
    float* qs     = ybar + 32;         // 32
    float* alphaS = qs + 32;           // 32
    float* mug    = alphaS + 32;       // 4
    float* rstdg  = mug + 4;           // 4

    const int b = blockIdx.y;
    const int o0 = blockIdx.x * 32;
    const int tid = threadIdx.x;

    for (int i = tid; i < KK * CC; i += 256) rf[i] = g_ref[b * KK * CC + i];
    for (int i = tid; i < KK * KK; i += 256) S2s[i] = g_S2[b * KK * KK + i];
    if (tid < KK) As[tid] = g_A[b * KK + tid];
    for (int i = tid; i < 32 * CC; i += 256) {
        int o = i >> 8, c = i & 255;
        pwS[o * 257 + c] = pw_w[(o0 + o) * CC + c];
    }
    __syncthreads();

    // M[k][o] = sum_c rf[k][c] * pw[o][c]
    {
        int oG = tid & 31, k0 = (tid >> 5) * 8;
        float acc[8] = {};
        for (int c = 0; c < CC; c++) {
            float pv = pwS[oG * 257 + c];
#pragma unroll
            for (int i = 0; i < 8; i++)
                acc[i] = fmaf(rf[(k0 + i) * CC + c], pv, acc[i]);
        }
#pragma unroll
        for (int i = 0; i < 8; i++) Ms[(k0 + i) * 33 + oG] = acc[i];
    }
    __syncthreads();

    // ybar_o = pw_b + sum_k (A_k/N) M[k][o]
    if (tid < 32) {
        float ssum = 0.f;
        for (int k = 0; k < KK; k++) ssum = fmaf(As[k], Ms[k * 33 + tid], ssum);
        float ab = ssum * (1.f / (float)HWN);
        abar[tid] = ab;
        ybar[tid] = pw_b[o0 + tid] + ab;
    }
    __syncthreads();

    // center: Mc = M - abar_o
    for (int i = tid; i < KK * 32; i += 256) {
        int k = i >> 5, o = i & 31;
        Ms[k * 33 + o] -= abar[o];
    }
    __syncthreads();

    // T[k][o] = sum_k2 S2[k][k2] * Mc[k2][o]
    for (int i = tid; i < KK * 32; i += 256) {
        int k = i >> 5, o = i & 31;
        float t = 0.f;
        for (int k2 = 0; k2 < KK; k2++)
            t = fmaf(S2s[k * KK + k2], Ms[k2 * 33 + o], t);
        pwS[k * 33 + o] = t;
    }
    __syncthreads();

    // q_o = sum_k Mc[k][o] * T[k][o]
    if (tid < 32) {
        float q = 0.f;
        for (int k = 0; k < KK; k++)
            q = fmaf(Ms[k * 33 + tid], pwS[k * 33 + tid], q);
        qs[tid] = q;
    }
    __syncthreads();

    if (tid < 4) {
        float mu = 0.f;
#pragma unroll
        for (int j = 0; j < 8; j++) mu += ybar[tid * 8 + j];
        mu *= 0.125f;
        float v = 0.f, vq = 0.f;
#pragma unroll
        for (int j = 0; j < 8; j++) {
            float d = ybar[tid * 8 + j] - mu;
            v = fmaf(d, d, v);
            vq += qs[tid * 8 + j];
        }
        v = v * 0.125f + vq * (1.f / (8.f * (float)HWN));
        mug[tid] = mu;
        rstdg[tid] = rsqrtf(v + EPS);
    }
    __syncthreads();

    if (tid < 32) {
        int o = o0 + tid, g = tid >> 3;
        float a = gn_g[o] * rstdg[g];
        alphaS[tid] = a;
        g_Bc[b * CC + o] = gn_b[o] + a * (ybar[tid] - mug[g]);
    }
    __syncthreads();

    for (int i = tid; i < KK * 32; i += 256) {
        int k = i >> 5, oG = i & 31;
        g_Mhat[(b * KK + k) * CC + o0 + oG] = alphaS[oG] * Ms[k * 33 + oG];
    }
}

// ---------------- pass 3: out = x + attn @ Mhat + Bc ----------------
__global__ __launch_bounds__(512, 1) void k3(const float* __restrict__ x,
                                             float* __restrict__ out) {
    extern __shared__ float s4[];
    float* atS = s4;               // [64][132]
    float* MhS = s4 + KK * 132;    // [64][256]
    float* BcS = MhS + KK * CC;    // [256]

    const int b = blockIdx.y;
    const int pix0 = blockIdx.x * PTILE;
    const int tid = threadIdx.x;

#pragma unroll
    for (int it = 0; it < 4; it++) {
        int idx = it * 512 + tid;          // 0..2047
        int k = idx >> 5, p4 = idx & 31;
        float4 v = *((const float4*)(g_attn + (size_t)(b * KK + k) * HWN + pix0) + p4);
        *((float4*)(atS + k * 132) + p4) = v;
    }
#pragma unroll
    for (int it = 0; it < 8; it++) {
        int idx = it * 512 + tid;          // 0..4095 float4
        ((float4*)MhS)[idx] = ((const float4*)(g_Mhat + (size_t)b * KK * CC))[idx];
    }
    if (tid < CC) BcS[tid] = g_Bc[b * CC + tid];
    __syncthreads();

    // thread = (pixel pair pp, 32-channel group cg); cg warp-uniform
    const int cg = tid >> 6;           // 0..7
    const int pp = tid & 63;           // 0..63 -> p0 = 2*pp
    const int p0 = 2 * pp;
    const int c0 = cg * 32;

    ull acc[2][16];
#pragma unroll
    for (int jc = 0; jc < 16; jc++) {
        ull bcv = *(const ull*)(BcS + c0 + 2 * jc);
        acc[0][jc] = bcv; acc[1][jc] = bcv;
    }

    for (int k = 0; k < KK; k++) {
        float2 af = *(const float2*)(atS + k * 132 + p0);
        ull ad0 = pk2(af.x, af.x), ad1 = pk2(af.y, af.y);
        const ulonglong2* mh = (const ulonglong2*)(MhS + k * CC + c0);
#pragma unroll
        for (int j4 = 0; j4 < 8; j4++) {
            ulonglong2 m = mh[j4];
            ffma2(acc[0][2 * j4],     ad0, m.x);
            ffma2(acc[0][2 * j4 + 1], ad0, m.y);
            ffma2(acc[1][2 * j4],     ad1, m.x);
            ffma2(acc[1][2 * j4 + 1], ad1, m.y);
        }
    }

    // epilogue: float2 loads/stores, fully coalesced (p0, p0+1 contiguous)
#pragma unroll
    for (int jc = 0; jc < 16; jc++) {
        float2 v0 = unpk(acc[0][jc]);   // (c0+2jc, c0+2jc+1) at pixel p0
        float2 v1 = unpk(acc[1][jc]);   // same channels at pixel p0+1
        int ch0 = c0 + 2 * jc;
        size_t base0 = ((size_t)b * CC + ch0) * HWN + pix0 + p0;
        size_t base1 = base0 + HWN;
        float2 xv0 = __ldcs((const float2*)(x + base0));
        float2 xv1 = __ldcs((const float2*)(x + base1));
        float2 o0 = make_float2(xv0.x + v0.x, xv0.y + v1.x);
        float2 o1 = make_float2(xv1.x + v0.y, xv1.y + v1.y);
        *(float2*)(out + base0) = o0;
        *(float2*)(out + base1) = o1;
    }
}

// ---------------- launch ----------------
extern "C" void kernel_launch(void* const* d_in, const int* in_sizes, int n_in,
                              void* d_out, int out_size) {
    const float* x       = (const float*)d_in[0];
    const float* centers = (const float*)d_in[1];
    const float* dw_w    = (const float*)d_in[2];
    const float* dw_b    = (const float*)d_in[3];
    const float* pw_w    = (const float*)d_in[4];
    const float* pw_b    = (const float*)d_in[5];
    const float* gn_g    = (const float*)d_in[6];
    const float* gn_b    = (const float*)d_in[7];
    float* out = (float*)d_out;

    const int SM1  = (CC * XS_STR + KK * 128) * 4;                       // 167936
    const int SM2A = (KK * CC + CC * 49) * 4;                            // 115712
    const int SM2B = (16384 + 4096 + 8224 + 2112 + 64 + 32 * 4 + 8) * 4; // 124064
    const int SM3  = (KK * 132 + KK * CC + CC) * 4;                      // 100352

    cudaFuncSetAttribute(k1,  cudaFuncAttributeMaxDynamicSharedMemorySize, SM1);
    cudaFuncSetAttribute(k2a, cudaFuncAttributeMaxDynamicSharedMemorySize, SM2A);
    cudaFuncSetAttribute(k2b, cudaFuncAttributeMaxDynamicSharedMemorySize, SM2B);
    cudaFuncSetAttribute(k3,  cudaFuncAttributeMaxDynamicSharedMemorySize, SM3);

    k_init<<<256, 256>>>(centers);
    k1<<<dim3(HWN / PTILE, BB), 512, SM1>>>(x);
    k2a<<<dim3(BB, 16), 256, SM2A>>>(dw_w, dw_b);
    k2b<<<dim3(8, BB), 256, SM2B>>>(pw_w, pw_b, gn_g, gn_b);
    k3<<<dim3(HWN / PTILE, BB), 512, SM3>>>(x, out);
}